// round 16
// baseline (speedup 1.0000x reference)
#include <cuda_runtime.h>
#include <cuda_fp16.h>
#include <math.h>
#include <stdint.h>

// ---------------- problem constants ----------------
#define Nn   27
#define NA   33
#define HID  256
#define REL  5
#define INW  322
#define FUSE_SCALE 0.1f
#define NEG  (-10000000000.0f)
#define MAXROWS 27648

// ---------------- scratch (device globals) -------------
__device__ float g_rz    [MAXROWS * 512];
__device__ float g_hn    [MAXROWS * 256];
__device__ float g_lgp   [MAXROWS * 128];
__device__ float g_attack[MAXROWS * 27];
__device__ float g_sender[MAXROWS * 32];
__device__ float g_qk    [MAXROWS * 128];
__device__ float g_qr    [MAXROWS * 20];
__device__ float g_qb    [MAXROWS * 4];
__device__ float g_gd    [MAXROWS * 512];
__device__ float g_hfb   [MAXROWS * 256];
__device__ float g_bpq   [384];
__device__ float g_bgd   [512];
__device__ float g_brz   [512];
__device__ float g_bp2p  [128];
// fp16 weight planes
__device__ __half g_W1h [256 * 352];
__device__ __half g_Brzh[512 * 512];
__device__ __half g_Wnih[256 * 256];
__device__ __half g_Wnhh[256 * 256];
__device__ __half g_Bpqh[384 * 256];
__device__ __half g_Wp2h[128 * 256];
__device__ __half g_Bgdh[512 * 288];
// fp16 activation planes (hi only)
__device__ __half g_inh [MAXROWS * 352];
__device__ __half g_cath[MAXROWS * 512];
__device__ __half g_hh  [MAXROWS * 256];
__device__ __half g_ph  [MAXROWS * 256];
__device__ __half g_fh  [MAXROWS * 288];

#define EPI_BIAS 1
#define EPI_BIAS_RELU 2
#define EPI_PLANES_RELU 3
#define EPI_MIX 4
#define EPI_GRU 5

// =================== helpers ===============
__device__ __forceinline__ uint32_t smem_u32(const void* p) {
    uint32_t a;
    asm("{ .reg .u64 t; cvta.to.shared.u64 t, %1; cvt.u32.u64 %0, t; }" : "=r"(a) : "l"(p));
    return a;
}
#define CP_ASYNC16(dst, src) \
    asm volatile("cp.async.cg.shared.global [%0], [%1], 16;" :: "r"(dst), "l"(src) : "memory")
#define CP_COMMIT() asm volatile("cp.async.commit_group;" ::: "memory")
#define CP_WAIT0()  asm volatile("cp.async.wait_group 0;" ::: "memory")
#define CP_WAIT1()  asm volatile("cp.async.wait_group 1;" ::: "memory")

__device__ __forceinline__ void ldsm4(uint32_t* d, uint32_t addr) {
    asm volatile("ldmatrix.sync.aligned.m8n8.x4.shared.b16 {%0,%1,%2,%3}, [%4];"
                 : "=r"(d[0]), "=r"(d[1]), "=r"(d[2]), "=r"(d[3]) : "r"(addr));
}
__device__ __forceinline__ void mma16816(float* c, const uint32_t* a, const uint32_t* b) {
    asm volatile("mma.sync.aligned.m16n8k16.row.col.f32.f16.f16.f32 "
                 "{%0,%1,%2,%3}, {%4,%5,%6,%7}, {%8,%9}, {%0,%1,%2,%3};"
                 : "+f"(c[0]), "+f"(c[1]), "+f"(c[2]), "+f"(c[3])
                 : "r"(a[0]), "r"(a[1]), "r"(a[2]), "r"(a[3]), "r"(b[0]), "r"(b[1]));
}
__device__ __forceinline__ float sigm(float x) { return 1.f / (1.f + expf(-x)); }

// =================== 3-stage pipelined mma.sync fp16 GEMM (single pass) ==============
#define PLNB   10240
#define STAGEB (2 * PLNB)
#define GSMEM  (3 * STAGEB)

template<int EPI>
__global__ void __launch_bounds__(256, 2)
gemm_mma(const __half* __restrict__ Ah, int lda,
         const __half* __restrict__ Bh, int ldb,
         const float* __restrict__ bias,
         float* __restrict__ C, __half* __restrict__ Ch,
         int ldc, int nChunks, int ldc2,
         const float* __restrict__ Grz, const float* __restrict__ Ghn,
         const float* __restrict__ Ghin, __half* __restrict__ Gfh)
{
    extern __shared__ __align__(16) char smx[];

    const int tid = threadIdx.x;
    const int wid = tid >> 5, lane = tid & 31;
    const int m0 = blockIdx.y * 128, n0 = blockIdx.x * 128;
    const int r = tid >> 1, hf = tid & 1;

    const uint32_t sbase = smem_u32(smx);
    const uint32_t stO = (uint32_t)r * 80 + hf * 32;

    const int warp_m = (wid & 1) * 64, warp_n = (wid >> 1) * 32;
    const uint32_t aOff = (uint32_t)(warp_m + (lane & 15)) * 80 + (lane >> 4) * 16;
    const uint32_t bRow = (uint32_t)(warp_n + (lane & 7) + ((lane >> 4) << 3));
    const uint32_t bOff = bRow * 80 + ((lane >> 3) & 1) * 16;

    float c[4][4][4];
#pragma unroll
    for (int mt = 0; mt < 4; mt++)
#pragma unroll
        for (int nt = 0; nt < 4; nt++)
#pragma unroll
            for (int q = 0; q < 4; q++) c[mt][nt][q] = 0.f;

    const __half* Ar = Ah + (size_t)(m0 + r) * lda + hf * 16;
    const __half* Br = Bh + (size_t)(n0 + r) * ldb + hf * 16;

    auto issue = [&](int ch, int st) {
        const int kc = ch * 32;
        const uint32_t base = sbase + st * STAGEB;
        CP_ASYNC16(base + stO,             Ar + kc);
        CP_ASYNC16(base + stO + 16,        Ar + kc + 8);
        CP_ASYNC16(base + PLNB + stO,      Br + kc);
        CP_ASYNC16(base + PLNB + stO + 16, Br + kc + 8);
        CP_COMMIT();
    };

    issue(0, 0);
    if (nChunks > 1) issue(1, 1);

    for (int ch = 0; ch < nChunks; ch++) {
        if (ch + 1 < nChunks) { CP_WAIT1(); } else { CP_WAIT0(); }
        __syncthreads();
        if (ch + 2 < nChunks) {
            int st = ch + 2;
            st = (st >= 3) ? ((st >= 6) ? ((st >= 9) ? ((st >= 12) ? ((st >= 15) ? st - 15 : st - 12) : st - 9) : st - 6) : st - 3) : st;
            issue(ch + 2, st);
        }

        int cs = ch;
        cs = (cs >= 3) ? ((cs >= 6) ? ((cs >= 9) ? ((cs >= 12) ? ((cs >= 15) ? cs - 15 : cs - 12) : cs - 9) : cs - 6) : cs - 3) : cs;
        const uint32_t base = sbase + cs * STAGEB;
        const uint32_t sA = base, sB = base + PLNB;
#pragma unroll
        for (int ks = 0; ks < 2; ks++) {
            const uint32_t ko = ks * 32;
            uint32_t aF[4][4], bF[4][2];
#pragma unroll
            for (int p = 0; p < 2; p++) {
                uint32_t t[4];
                ldsm4(t, sB + bOff + ko + p * (16 * 80));
                bF[2 * p][0] = t[0]; bF[2 * p][1] = t[1];
                bF[2 * p + 1][0] = t[2]; bF[2 * p + 1][1] = t[3];
            }
#pragma unroll
            for (int mt = 0; mt < 4; mt++) ldsm4(aF[mt], sA + aOff + ko + mt * (16 * 80));
#pragma unroll
            for (int mt = 0; mt < 4; mt++)
#pragma unroll
                for (int nt = 0; nt < 4; nt++) mma16816(c[mt][nt], aF[mt], bF[nt]);
        }
        __syncthreads();
    }

    // ---- epilogue ----
    const bool mixp = (EPI == EPI_MIX) && (n0 < 256);
    const bool planes = (EPI == EPI_PLANES_RELU) || mixp;
    const bool relu = (EPI == EPI_BIAS_RELU) || planes;
#pragma unroll
    for (int mt = 0; mt < 4; mt++) {
        const int row = m0 + warp_m + mt * 16 + (lane >> 2);
#pragma unroll
        for (int nt = 0; nt < 4; nt++) {
            const int col = n0 + warp_n + nt * 8 + (lane & 3) * 2;
            const float b0 = bias[col], b1 = bias[col + 1];
            float v0 = c[mt][nt][0] + b0, v1 = c[mt][nt][1] + b1;
            float v2 = c[mt][nt][2] + b0, v3 = c[mt][nt][3] + b1;
            if (relu) {
                v0 = fmaxf(v0, 0.f); v1 = fmaxf(v1, 0.f);
                v2 = fmaxf(v2, 0.f); v3 = fmaxf(v3, 0.f);
            }
            if (EPI == EPI_GRU) {
                // v* are inn pre-activations; finish the GRU here.
#pragma unroll
                for (int e = 0; e < 4; e++) {
                    const int rw = row + (e >> 1) * 8;
                    const int cl = col + (e & 1);
                    const float v = (e == 0) ? v0 : (e == 1) ? v1 : (e == 2) ? v2 : v3;
                    const size_t rb = (size_t)rw * 512;
                    const float rg = sigm(Grz[rb + cl]);
                    const float zg = sigm(Grz[rb + 256 + cl]);
                    const float ng = tanhf(v + rg * Ghn[(size_t)rw * 256 + cl]);
                    const float hv = (1.f - zg) * ng + zg * Ghin[(size_t)rw * 256 + cl];
                    C[(size_t)rw * 256 + cl] = hv;
                    const __half hb = __float2half(hv);
                    Ch[(size_t)rw * 256 + cl] = hb;
                    Gfh[(size_t)rw * 288 + cl] = hb;
                }
            } else if (planes) {
                *(__half2*)(Ch + (size_t)row * ldc + col) =
                    __halves2half2(__float2half(v0), __float2half(v1));
                *(__half2*)(Ch + (size_t)(row + 8) * ldc + col) =
                    __halves2half2(__float2half(v2), __float2half(v3));
            } else if (EPI == EPI_MIX) {
                const int c2 = col - 256;
                *(float2*)(C + (size_t)row * ldc2 + c2) = make_float2(v0, v1);
                *(float2*)(C + (size_t)(row + 8) * ldc2 + c2) = make_float2(v2, v3);
            } else {
                *(float2*)(C + (size_t)row * ldc + col) = make_float2(v0, v1);
                *(float2*)(C + (size_t)(row + 8) * ldc + col) = make_float2(v2, v3);
            }
        }
    }
}

// ================= activation convert: fp32 -> fp16 =================
__global__ void conv_h(const float* __restrict__ src, __half* __restrict__ hi,
                       int Mrows, int K, int Kpad, int ldo, int off)
{
    int idx = blockIdx.x * blockDim.x + threadIdx.x;
    if (idx >= Mrows * Kpad) return;
    int m = idx / Kpad, k = idx - m * Kpad;
    float v = (k < K) ? src[(size_t)m * K + k] : 0.f;
    hi[(size_t)m * ldo + off + k] = __float2half(v);
}

// ================= one-shot weight prep =================
#define T0 (256*352)
#define T1 (512*512)
#define T2 (256*256)
#define T3 (256*256)
#define T4 (384*256)
#define T5 (128*256)
#define T6 (512*288)
#define T7 (384+512+512+128)
#define TTOT (T0+T1+T2+T3+T4+T5+T6+T7)

__global__ void prep_all(const float* __restrict__ W1,  const float* __restrict__ Wih,
                         const float* __restrict__ Whh, const float* __restrict__ Wp1,
                         const float* __restrict__ Wp2, const float* __restrict__ Wq,
                         const float* __restrict__ Wk,  const float* __restrict__ Wg1,
                         const float* __restrict__ Wd1,
                         const float* __restrict__ bp1, const float* __restrict__ bq,
                         const float* __restrict__ bg1, const float* __restrict__ bd1,
                         const float* __restrict__ bih, const float* __restrict__ bhh,
                         const float* __restrict__ bp2,
                         __half* __restrict__ W1h,  __half* __restrict__ Brzh,
                         __half* __restrict__ Wnih, __half* __restrict__ Wnhh,
                         __half* __restrict__ Bpqh, __half* __restrict__ Wp2h,
                         __half* __restrict__ Bgdh,
                         float* __restrict__ pbpq, float* __restrict__ pbgd,
                         float* __restrict__ pbrz, float* __restrict__ pbp2p)
{
    int idx = blockIdx.x * blockDim.x + threadIdx.x;
    if (idx >= TTOT) return;
    float src;
    __half* dst;
    int off;
    if (idx < T0) {
        off = idx;
        int k = off % 352;
        src = (k < 322) ? W1[(off / 352) * 322 + k] : 0.f;
        dst = W1h;
    } else if (idx < T0 + T1) {
        off = idx - T0;
        int n = off >> 9, k = off & 511;
        src = (k < 256) ? Wih[n * 256 + k] : Whh[n * 256 + (k - 256)];
        dst = Brzh;
    } else if (idx < T0 + T1 + T2) {
        off = idx - T0 - T1;
        src = Wih[512 * 256 + off];
        dst = Wnih;
    } else if (idx < T0 + T1 + T2 + T3) {
        off = idx - T0 - T1 - T2;
        src = Whh[512 * 256 + off];
        dst = Wnhh;
    } else if (idx < T0 + T1 + T2 + T3 + T4) {
        off = idx - T0 - T1 - T2 - T3;
        int rr = off >> 8, cc = off & 255;
        if (rr < 256) src = Wp1[rr * 256 + cc];
        else if (rr < 320) src = Wq[(rr - 256) * 256 + cc];
        else src = Wk[(size_t)(rr - 320) * (HID + REL) + cc];
        dst = Bpqh;
    } else if (idx < T0 + T1 + T2 + T3 + T4 + T5) {
        off = idx - T0 - T1 - T2 - T3 - T4;
        int n = off >> 8;
        src = (n < NA) ? Wp2[n * 256 + (off & 255)] : 0.f;
        dst = Wp2h;
    } else if (idx < T0 + T1 + T2 + T3 + T4 + T5 + T6) {
        off = idx - T0 - T1 - T2 - T3 - T4 - T5;
        int rr = off / 288, cc = off % 288;
        src = (rr < 256) ? Wg1[rr * 288 + cc] : Wd1[(rr - 256) * 288 + cc];
        dst = Bgdh;
    } else {
        off = idx - (T0 + T1 + T2 + T3 + T4 + T5 + T6);
        if (off < 384) {
            pbpq[off] = (off < 256) ? bp1[off] : ((off < 320) ? bq[off - 256] : 0.f);
        } else if (off < 896) {
            int o = off - 384; pbgd[o] = (o < 256) ? bg1[o] : bd1[o - 256];
        } else if (off < 1408) {
            int o = off - 896; pbrz[o] = bih[o] + bhh[o];
        } else {
            int o = off - 1408; pbp2p[o] = (o < NA) ? bp2[o] : 0.f;
        }
        return;
    }
    dst[off] = __float2half(src);
}

// ================= logits post (padded logits, ld=128) =================
__global__ void __launch_bounds__(256)
logits_post(const float* __restrict__ logits, const float* __restrict__ Wv,
            const float* __restrict__ bv,
            float* __restrict__ out, float* __restrict__ attack,
            float* __restrict__ sender)
{
    __shared__ float Wvs[32 * 29];
    __shared__ float bvs[32];
    __shared__ float vs[8][29];
    int tid = threadIdx.x;
    for (int t = tid; t < 32 * 29; t += 256) Wvs[t] = Wv[t];
    if (tid < 32) bvs[tid] = bv[tid];
    int w = tid >> 5, l = tid & 31;
    int row = blockIdx.x * 8 + w;
    const float* lrow = logits + (size_t)row * 128;
    float al = (l < 27) ? lrow[6 + l] : -INFINITY;
    float mx = al;
#pragma unroll
    for (int o = 16; o > 0; o >>= 1) mx = fmaxf(mx, __shfl_xor_sync(0xffffffffu, mx, o));
    float e = (l < 27) ? expf(al - mx) : 0.f;
    float sum = e;
#pragma unroll
    for (int o = 16; o > 0; o >>= 1) sum += __shfl_xor_sync(0xffffffffu, sum, o);
    float inv = 1.f / sum;
    if (l < 27) vs[w][l] = e * inv;
    if (l == 27) vs[w][27] = 1.0f;
    if (l == 28) vs[w][28] = inv;
    if (l < 27) attack[(size_t)row * 27 + l] = al;
    if (l < 6)  out[(size_t)row * 33 + l] = lrow[l];
    __syncthreads();
    float s = bvs[l];
#pragma unroll
    for (int r = 0; r < 29; r++) s += vs[w][r] * Wvs[l * 29 + r];
    sender[(size_t)row * 32 + l] = s;
}

// ================= qr / qb precompute =================
__global__ void qr_kernel(const float* __restrict__ qk, const float* __restrict__ Wk,
                          const float* __restrict__ bk,
                          float* __restrict__ qr, float* __restrict__ qb, int rows)
{
    int idx = blockIdx.x * blockDim.x + threadIdx.x;
    if (idx >= rows * 4) return;
    int row = idx >> 2, h = idx & 3;
    const float* qp = qk + (size_t)row * 128 + h * 16;
    float acc[5] = {0.f, 0.f, 0.f, 0.f, 0.f};
    float accb = 0.f;
#pragma unroll
    for (int d = 0; d < 16; d++) {
        float qd = qp[d];
        const float* wrow = Wk + (size_t)(h * 16 + d) * (HID + REL) + HID;
#pragma unroll
        for (int r = 0; r < 5; r++) acc[r] += qd * wrow[r];
        accb += qd * bk[h * 16 + d];
    }
#pragma unroll
    for (int r = 0; r < 5; r++) qr[(size_t)row * 20 + h * 5 + r] = acc[r];
    qb[(size_t)row * 4 + h] = accb;
}

// ================= batched attention =================
__global__ void __launch_bounds__(256)
attn_batch(const float* __restrict__ qk, const float* __restrict__ qr,
           const float* __restrict__ qb, const float* __restrict__ rel,
           const float* __restrict__ sender,
           const float* __restrict__ nullk, const float* __restrict__ nullv,
           const float* __restrict__ ln_g, const float* __restrict__ ln_b,
           __half* __restrict__ fh)
{
    __shared__ float qk_s[27 * 128];
    __shared__ float sender_s[27 * 32];
    __shared__ float rel_s[27 * 27 * 5];
    __shared__ float qr_s[27 * 20];
    __shared__ float qb_s[27 * 4];
    __shared__ float nk_s[64];
    __shared__ float nv_s[32];
    __shared__ float sc[27 * 112];

    const int b = blockIdx.x;
    const int tid = threadIdx.x;
    const size_t rbase = (size_t)b * 27;

    for (int t = tid; t < 27 * 128; t += 256) qk_s[t] = qk[rbase * 128 + t];
    for (int t = tid; t < 27 * 32; t += 256) sender_s[t] = sender[rbase * 32 + t];
    for (int t = tid; t < 27 * 27 * 5; t += 256) rel_s[t] = rel[(size_t)b * (27 * 27 * 5) + t];
    for (int t = tid; t < 27 * 20; t += 256) qr_s[t] = qr[rbase * 20 + t];
    for (int t = tid; t < 27 * 4; t += 256) qb_s[t] = qb[rbase * 4 + t];
    if (tid < 64) nk_s[tid] = nullk[tid];
    if (tid >= 64 && tid < 96) nv_s[tid - 64] = nullv[tid - 64];
    __syncthreads();

    for (int t = tid; t < 27 * 112; t += 256) {
        int i = t / 112;
        int rem = t - i * 112;
        int j = rem >> 2, h = rem & 3;
        float s;
        if (j == 27) {
            float d = 0.f;
#pragma unroll
            for (int dd = 0; dd < 16; dd++) d += qk_s[i * 128 + h * 16 + dd] * nk_s[h * 16 + dd];
            s = 0.25f * d;
        } else if (j == i) {
            s = NEG;
        } else {
            float d = qb_s[i * 4 + h];
#pragma unroll
            for (int dd = 0; dd < 16; dd++)
                d += qk_s[i * 128 + h * 16 + dd] * qk_s[j * 128 + 64 + h * 16 + dd];
            const float* rr = &rel_s[(i * 27 + j) * 5];
#pragma unroll
            for (int r = 0; r < 5; r++) d += qr_s[i * 20 + h * 5 + r] * rr[r];
            s = 0.25f * d;
        }
        sc[t] = s;
    }
    __syncthreads();

    for (int t = tid; t < 108; t += 256) {
        int i = t >> 2, h = t & 3;
        float* scp = &sc[i * 112 + h];
        float t0 = -INFINITY, t1 = -INFINITY, t2 = -INFINITY, t3 = -INFINITY;
#pragma unroll
        for (int j = 0; j < 28; j++) {
            float v = scp[j * 4];
            if (v > t0)      { t3 = t2; t2 = t1; t1 = t0; t0 = v; }
            else if (v > t1) { t3 = t2; t2 = t1; t1 = v; }
            else if (v > t2) { t3 = t2; t2 = v; }
            else if (v > t3) { t3 = v; }
        }
        float thr = t3, mxv = t0, sum = 0.f;
        float e[28];
#pragma unroll
        for (int j = 0; j < 28; j++) {
            float v = scp[j * 4];
            float ev = (v >= thr) ? expf(v - mxv) : 0.f;
            e[j] = ev; sum += ev;
        }
        float inv = 1.f / sum;
#pragma unroll
        for (int j = 0; j < 28; j++) scp[j * 4] = e[j] * inv;
    }
    __syncthreads();

    int w = tid >> 5, l = tid & 31;
    int h = l >> 3;
    for (int i = w; i < 27; i += 8) {
        const float* scp = &sc[i * 112];
        float m = scp[108 + h] * nv_s[l];
#pragma unroll
        for (int j = 0; j < 27; j++) m += scp[j * 4 + h] * sender_s[j * 32 + l];
        float s = m, s2 = m * m;
#pragma unroll
        for (int o = 16; o > 0; o >>= 1) {
            s  += __shfl_xor_sync(0xffffffffu, s, o);
            s2 += __shfl_xor_sync(0xffffffffu, s2, o);
        }
        float mu = s * (1.f / 32.f);
        float var = s2 * (1.f / 32.f) - mu * mu;
        float nm = (m - mu) * rsqrtf(var + 1e-5f) * ln_g[l] + ln_b[l];
        fh[(rbase + i) * 288 + 256 + l] = __float2half(nm);
    }
}

// ================= final (32 rows per block) =================
__global__ void __launch_bounds__(256)
final_kernel(const float* __restrict__ gd,
             const float* __restrict__ Wg2, const float* __restrict__ bg2,
             const float* __restrict__ Wd2, const float* __restrict__ bd2,
             const float* __restrict__ attack,
             float* __restrict__ out)
{
    __shared__ float Wd2s[256 * 28];
    __shared__ float wg2s[256];
    int tid = threadIdx.x;
    for (int t = tid; t < 27 * 256; t += 256) {
        int l = t >> 8, k = t & 255;
        Wd2s[k * 28 + l] = Wd2[t];
    }
    if (tid < 256) wg2s[tid] = Wg2[tid];
    __syncthreads();

    int w = tid >> 5, l = tid & 31;
    const float bg2v = bg2[0];
    const float bd2v = (l < 27) ? bd2[l] : 0.f;
#pragma unroll
    for (int rr = 0; rr < 4; rr++) {
        int row = blockIdx.x * 32 + rr * 8 + w;
        const float* g1r = gd + (size_t)row * 512;
        const float* d1r = g1r + 256;
        float gs = 0.f;
#pragma unroll
        for (int i = 0; i < 8; i++) gs += g1r[l + i * 32] * wg2s[l + i * 32];
#pragma unroll
        for (int o = 16; o > 0; o >>= 1) gs += __shfl_xor_sync(0xffffffffu, gs, o);
        float gate = 1.f / (1.f + expf(-(gs + bg2v)));
        if (l < 27) {
            float d = bd2v;
#pragma unroll 8
            for (int k = 0; k < 256; k++) d += d1r[k] * Wd2s[k * 28 + l];
            out[(size_t)row * 33 + 6 + l] = attack[(size_t)row * 27 + l] + FUSE_SCALE * gate * d;
        }
    }
}

// ================= host launcher =================
static float* sym(const void* symbol)
{
    void* p = nullptr;
    cudaGetSymbolAddress(&p, symbol);
    return (float*)p;
}
static __half* symh(const void* symbol)
{
    void* p = nullptr;
    cudaGetSymbolAddress(&p, symbol);
    return (__half*)p;
}

extern "C" void kernel_launch(void* const* d_in, const int* in_sizes, int n_in,
                              void* d_out, int out_size)
{
    const float* inputs = (const float*)d_in[0];
    const float* hidden = (const float*)d_in[1];
    const float* rel    = (const float*)d_in[2];
    const float* W1     = (const float*)d_in[3];
    const float* b1     = (const float*)d_in[4];
    const float* Wih    = (const float*)d_in[5];
    const float* bih    = (const float*)d_in[6];
    const float* Whh    = (const float*)d_in[7];
    const float* bhh    = (const float*)d_in[8];
    const float* Wp1    = (const float*)d_in[9];
    const float* bp1    = (const float*)d_in[10];
    const float* Wp2    = (const float*)d_in[11];
    const float* bp2    = (const float*)d_in[12];
    const float* Wq     = (const float*)d_in[13];
    const float* bq     = (const float*)d_in[14];
    const float* Wk     = (const float*)d_in[15];
    const float* bk     = (const float*)d_in[16];
    const float* Wv     = (const float*)d_in[17];
    const float* bv     = (const float*)d_in[18];
    const float* ln_g   = (const float*)d_in[19];
    const float* ln_b   = (const float*)d_in[20];
    const float* Wg1    = (const float*)d_in[21];
    const float* bg1    = (const float*)d_in[22];
    const float* Wg2    = (const float*)d_in[23];
    const float* bg2    = (const float*)d_in[24];
    const float* Wd1    = (const float*)d_in[25];
    const float* bd1    = (const float*)d_in[26];
    const float* Wd2    = (const float*)d_in[27];
    const float* bd2    = (const float*)d_in[28];
    const float* nullk  = (const float*)d_in[29];
    const float* nullv  = (const float*)d_in[30];

    const int rows = in_sizes[0] / INW;    // 27648
    const int bs = rows / Nn;
    float* out = (float*)d_out;

    float* prz     = sym(g_rz);
    float* phn     = sym(g_hn);
    float* plgp    = sym(g_lgp);
    float* pattack = sym(g_attack);
    float* psender = sym(g_sender);
    float* pqk     = sym(g_qk);
    float* pqr     = sym(g_qr);
    float* pqb     = sym(g_qb);
    float* pgd     = sym(g_gd);
    float* pbpq    = sym(g_bpq);
    float* pbgd    = sym(g_bgd);
    float* pbrz    = sym(g_brz);
    float* pbp2p   = sym(g_bp2p);

    __half *pW1h = symh(g_W1h);
    __half *pBrzh = symh(g_Brzh);
    __half *pWnih = symh(g_Wnih);
    __half *pWnhh = symh(g_Wnhh);
    __half *pBpqh = symh(g_Bpqh);
    __half *pWp2h = symh(g_Wp2h);
    __half *pBgdh = symh(g_Bgdh);
    __half *pinh = symh(g_inh);
    __half *pcath = symh(g_cath);
    __half *phh = symh(g_hh);
    __half *pph = symh(g_ph);
    __half *pfh = symh(g_fh);

    float* hout = (out_size >= rows * (NA + HID)) ? out + (size_t)rows * NA : sym(g_hfb);

    const int MB = rows / 128;   // 216

    cudaFuncSetAttribute((const void*)gemm_mma<EPI_BIAS>,        cudaFuncAttributeMaxDynamicSharedMemorySize, GSMEM);
    cudaFuncSetAttribute((const void*)gemm_mma<EPI_PLANES_RELU>, cudaFuncAttributeMaxDynamicSharedMemorySize, GSMEM);
    cudaFuncSetAttribute((const void*)gemm_mma<EPI_MIX>,         cudaFuncAttributeMaxDynamicSharedMemorySize, GSMEM);
    cudaFuncSetAttribute((const void*)gemm_mma<EPI_BIAS_RELU>,   cudaFuncAttributeMaxDynamicSharedMemorySize, GSMEM);
    cudaFuncSetAttribute((const void*)gemm_mma<EPI_GRU>,         cudaFuncAttributeMaxDynamicSharedMemorySize, GSMEM);

    // side stream + fork/join events
    static cudaStream_t s1 = nullptr;
    static cudaEvent_t e0 = nullptr, eH = nullptr, eN = nullptr, e2 = nullptr, eQ = nullptr;
    if (!s1) {
        cudaStreamCreateWithFlags(&s1, cudaStreamNonBlocking);
        cudaEventCreateWithFlags(&e0, cudaEventDisableTiming);
        cudaEventCreateWithFlags(&eH, cudaEventDisableTiming);
        cudaEventCreateWithFlags(&eN, cudaEventDisableTiming);
        cudaEventCreateWithFlags(&e2, cudaEventDisableTiming);
        cudaEventCreateWithFlags(&eQ, cudaEventDisableTiming);
    }

    // --- prep (stream 0) ---
    prep_all<<<(TTOT + 255) / 256, 256>>>(W1, Wih, Whh, Wp1, Wp2, Wq, Wk, Wg1, Wd1,
                                          bp1, bq, bg1, bd1, bih, bhh, bp2,
                                          pW1h, pBrzh, pWnih, pWnhh, pBpqh, pWp2h, pBgdh,
                                          pbpq, pbgd, pbrz, pbp2p);
    conv_h<<<(rows * 352 + 255) / 256, 256>>>(inputs, pinh, rows, 322, 352, 352, 0);

    // fork: s1 does conv(hidden) -> hn GEMM
    cudaEventRecord(e0, 0);
    cudaStreamWaitEvent(s1, e0, 0);
    conv_h<<<(rows * 256 + 255) / 256, 256, 0, s1>>>(hidden, pcath, rows, 256, 256, 512, 256);
    cudaEventRecord(eH, s1);
    gemm_mma<EPI_BIAS><<<dim3(2, MB), 256, GSMEM, s1>>>(pcath + 256, 512, pWnhh, 256,
                                                        bhh + 512, phn, nullptr, 256, 8, 0,
                                                        nullptr, nullptr, nullptr, nullptr);
    cudaEventRecord(eN, s1);

    // main chain (stream 0)
    gemm_mma<EPI_PLANES_RELU><<<dim3(2, MB), 256, GSMEM>>>(pinh, 352, pW1h, 352, b1,
                                                           nullptr, pcath, 512, 11, 0,
                                                           nullptr, nullptr, nullptr, nullptr);
    cudaStreamWaitEvent(0, eH, 0);
    gemm_mma<EPI_BIAS><<<dim3(4, MB), 256, GSMEM>>>(pcath, 512, pBrzh, 512, pbrz,
                                                    prz, nullptr, 512, 16, 0,
                                                    nullptr, nullptr, nullptr, nullptr);
    // fused inn GEMM + GRU: writes hout, h-plane, fusion-plane
    cudaStreamWaitEvent(0, eN, 0);
    gemm_mma<EPI_GRU><<<dim3(2, MB), 256, GSMEM>>>(pcath, 512, pWnih, 256, bih + 512,
                                                   hout, phh, 256, 8, 0,
                                                   prz, phn, hidden, pfh);
    // merged [p-planes | qk]
    gemm_mma<EPI_MIX><<<dim3(3, MB), 256, GSMEM>>>(phh, 256, pBpqh, 256, pbpq,
                                                   pqk, pph, 256, 8, 128,
                                                   nullptr, nullptr, nullptr, nullptr);
    cudaEventRecord(e2, 0);
    cudaStreamWaitEvent(s1, e2, 0);
    qr_kernel<<<(rows * 4 + 127) / 128, 128, 0, s1>>>(pqk, Wk, bk, pqr, pqb, rows);
    cudaEventRecord(eQ, s1);
    gemm_mma<EPI_BIAS><<<dim3(1, MB), 256, GSMEM>>>(pph, 256, pWp2h, 256, pbp2p,
                                                    plgp, nullptr, 128, 8, 0,
                                                    nullptr, nullptr, nullptr, nullptr);
    logits_post<<<rows / 8, 256>>>(plgp, Wv, bv, out, pattack, psender);
    cudaStreamWaitEvent(0, eQ, 0);
    attn_batch<<<bs, 256>>>(pqk, pqr, pqb, rel, psender, nullk, nullv, ln_g, ln_b, pfh);
    gemm_mma<EPI_BIAS_RELU><<<dim3(4, MB), 256, GSMEM>>>(pfh, 288, pBgdh, 288, pbgd,
                                                         pgd, nullptr, 512, 9, 0,
                                                         nullptr, nullptr, nullptr, nullptr);
    final_kernel<<<rows / 32, 256>>>(pgd, Wg2, bg2, Wd2, bd2, pattack, out);
}

// round 17
// speedup vs baseline: 1.1134x; 1.1134x over previous
#include <cuda_runtime.h>
#include <cuda_fp16.h>
#include <math.h>
#include <stdint.h>

// ---------------- problem constants ----------------
#define Nn   27
#define NA   33
#define HID  256
#define REL  5
#define INW  322
#define FUSE_SCALE 0.1f
#define NEG  (-10000000000.0f)
#define MAXROWS 27648

// ---------------- scratch (device globals) -------------
__device__ float g_rz    [MAXROWS * 512];
__device__ float g_inn   [MAXROWS * 256];
__device__ float g_hn    [MAXROWS * 256];
__device__ float g_lgp   [MAXROWS * 128];
__device__ float g_attack[MAXROWS * 27];
__device__ float g_sender[MAXROWS * 32];
__device__ float g_qk    [MAXROWS * 128];
__device__ float g_qr    [MAXROWS * 20];
__device__ float g_qb    [MAXROWS * 4];
__device__ float g_gd    [MAXROWS * 512];
__device__ float g_hfb   [MAXROWS * 256];
__device__ float g_bpq   [384];
__device__ float g_bgd   [512];
__device__ float g_brz   [512];
__device__ float g_bp2p  [128];
// fp16 weight planes
__device__ __half g_W1h [256 * 352];
__device__ __half g_Brzh[512 * 512];
__device__ __half g_Wnih[256 * 256];
__device__ __half g_Wnhh[256 * 256];
__device__ __half g_Bpqh[384 * 256];
__device__ __half g_Wp2h[128 * 256];
__device__ __half g_Bgdh[512 * 288];
// fp16 activation planes (hi only)
__device__ __half g_inh [MAXROWS * 352];
__device__ __half g_cath[MAXROWS * 512];
__device__ __half g_hh  [MAXROWS * 256];
__device__ __half g_ph  [MAXROWS * 256];
__device__ __half g_fh  [MAXROWS * 288];

#define EPI_BIAS 1
#define EPI_BIAS_RELU 2
#define EPI_PLANES_RELU 3
#define EPI_MIX 4

// =================== helpers ===============
__device__ __forceinline__ uint32_t smem_u32(const void* p) {
    uint32_t a;
    asm("{ .reg .u64 t; cvta.to.shared.u64 t, %1; cvt.u32.u64 %0, t; }" : "=r"(a) : "l"(p));
    return a;
}
#define CP_ASYNC16(dst, src) \
    asm volatile("cp.async.cg.shared.global [%0], [%1], 16;" :: "r"(dst), "l"(src) : "memory")
#define CP_COMMIT() asm volatile("cp.async.commit_group;" ::: "memory")
#define CP_WAIT0()  asm volatile("cp.async.wait_group 0;" ::: "memory")
#define CP_WAIT1()  asm volatile("cp.async.wait_group 1;" ::: "memory")

__device__ __forceinline__ void ldsm4(uint32_t* d, uint32_t addr) {
    asm volatile("ldmatrix.sync.aligned.m8n8.x4.shared.b16 {%0,%1,%2,%3}, [%4];"
                 : "=r"(d[0]), "=r"(d[1]), "=r"(d[2]), "=r"(d[3]) : "r"(addr));
}
__device__ __forceinline__ void mma16816(float* c, const uint32_t* a, const uint32_t* b) {
    asm volatile("mma.sync.aligned.m16n8k16.row.col.f32.f16.f16.f32 "
                 "{%0,%1,%2,%3}, {%4,%5,%6,%7}, {%8,%9}, {%0,%1,%2,%3};"
                 : "+f"(c[0]), "+f"(c[1]), "+f"(c[2]), "+f"(c[3])
                 : "r"(a[0]), "r"(a[1]), "r"(a[2]), "r"(a[3]), "r"(b[0]), "r"(b[1]));
}

// =================== 3-stage pipelined mma.sync fp16 GEMM (single pass) ==============
#define PLNB   10240
#define STAGEB (2 * PLNB)
#define GSMEM  (3 * STAGEB)

template<int EPI>
__global__ void __launch_bounds__(256, 2)
gemm_mma(const __half* __restrict__ Ah, int lda,
         const __half* __restrict__ Bh, int ldb,
         const float* __restrict__ bias,
         float* __restrict__ C, __half* __restrict__ Ch,
         int ldc, int nChunks, int ldc2)
{
    extern __shared__ __align__(16) char smx[];

    const int tid = threadIdx.x;
    const int wid = tid >> 5, lane = tid & 31;
    const int m0 = blockIdx.y * 128, n0 = blockIdx.x * 128;
    const int r = tid >> 1, hf = tid & 1;

    const uint32_t sbase = smem_u32(smx);
    const uint32_t stO = (uint32_t)r * 80 + hf * 32;

    const int warp_m = (wid & 1) * 64, warp_n = (wid >> 1) * 32;
    const uint32_t aOff = (uint32_t)(warp_m + (lane & 15)) * 80 + (lane >> 4) * 16;
    const uint32_t bRow = (uint32_t)(warp_n + (lane & 7) + ((lane >> 4) << 3));
    const uint32_t bOff = bRow * 80 + ((lane >> 3) & 1) * 16;

    float c[4][4][4];
#pragma unroll
    for (int mt = 0; mt < 4; mt++)
#pragma unroll
        for (int nt = 0; nt < 4; nt++)
#pragma unroll
            for (int q = 0; q < 4; q++) c[mt][nt][q] = 0.f;

    const __half* Ar = Ah + (size_t)(m0 + r) * lda + hf * 16;
    const __half* Br = Bh + (size_t)(n0 + r) * ldb + hf * 16;

    auto issue = [&](int ch, int st) {
        const int kc = ch * 32;
        const uint32_t base = sbase + st * STAGEB;
        CP_ASYNC16(base + stO,             Ar + kc);
        CP_ASYNC16(base + stO + 16,        Ar + kc + 8);
        CP_ASYNC16(base + PLNB + stO,      Br + kc);
        CP_ASYNC16(base + PLNB + stO + 16, Br + kc + 8);
        CP_COMMIT();
    };

    issue(0, 0);
    if (nChunks > 1) issue(1, 1);

    for (int ch = 0; ch < nChunks; ch++) {
        if (ch + 1 < nChunks) { CP_WAIT1(); } else { CP_WAIT0(); }
        __syncthreads();
        if (ch + 2 < nChunks) {
            int st = ch + 2;
            st = (st >= 3) ? ((st >= 6) ? ((st >= 9) ? ((st >= 12) ? ((st >= 15) ? st - 15 : st - 12) : st - 9) : st - 6) : st - 3) : st;
            issue(ch + 2, st);
        }

        int cs = ch;
        cs = (cs >= 3) ? ((cs >= 6) ? ((cs >= 9) ? ((cs >= 12) ? ((cs >= 15) ? cs - 15 : cs - 12) : cs - 9) : cs - 6) : cs - 3) : cs;
        const uint32_t base = sbase + cs * STAGEB;
        const uint32_t sA = base, sB = base + PLNB;
#pragma unroll
        for (int ks = 0; ks < 2; ks++) {
            const uint32_t ko = ks * 32;
            uint32_t aF[4][4], bF[4][2];
#pragma unroll
            for (int p = 0; p < 2; p++) {
                uint32_t t[4];
                ldsm4(t, sB + bOff + ko + p * (16 * 80));
                bF[2 * p][0] = t[0]; bF[2 * p][1] = t[1];
                bF[2 * p + 1][0] = t[2]; bF[2 * p + 1][1] = t[3];
            }
#pragma unroll
            for (int mt = 0; mt < 4; mt++) ldsm4(aF[mt], sA + aOff + ko + mt * (16 * 80));
#pragma unroll
            for (int mt = 0; mt < 4; mt++)
#pragma unroll
                for (int nt = 0; nt < 4; nt++) mma16816(c[mt][nt], aF[mt], bF[nt]);
        }
        __syncthreads();
    }

    // ---- epilogue ----
    const bool mixp = (EPI == EPI_MIX) && (n0 < 256);
    const bool planes = (EPI == EPI_PLANES_RELU) || mixp;
    const bool relu = (EPI == EPI_BIAS_RELU) || planes;
#pragma unroll
    for (int mt = 0; mt < 4; mt++) {
        const int row = m0 + warp_m + mt * 16 + (lane >> 2);
#pragma unroll
        for (int nt = 0; nt < 4; nt++) {
            const int col = n0 + warp_n + nt * 8 + (lane & 3) * 2;
            const float b0 = bias[col], b1 = bias[col + 1];
            float v0 = c[mt][nt][0] + b0, v1 = c[mt][nt][1] + b1;
            float v2 = c[mt][nt][2] + b0, v3 = c[mt][nt][3] + b1;
            if (relu) {
                v0 = fmaxf(v0, 0.f); v1 = fmaxf(v1, 0.f);
                v2 = fmaxf(v2, 0.f); v3 = fmaxf(v3, 0.f);
            }
            if (planes) {
                *(__half2*)(Ch + (size_t)row * ldc + col) =
                    __halves2half2(__float2half(v0), __float2half(v1));
                *(__half2*)(Ch + (size_t)(row + 8) * ldc + col) =
                    __halves2half2(__float2half(v2), __float2half(v3));
            } else if (EPI == EPI_MIX) {
                const int c2 = col - 256;
                *(float2*)(C + (size_t)row * ldc2 + c2) = make_float2(v0, v1);
                *(float2*)(C + (size_t)(row + 8) * ldc2 + c2) = make_float2(v2, v3);
            } else {
                *(float2*)(C + (size_t)row * ldc + col) = make_float2(v0, v1);
                *(float2*)(C + (size_t)(row + 8) * ldc + col) = make_float2(v2, v3);
            }
        }
    }
}

// ================= activation convert: fp32 -> fp16 (hi only) =================
__global__ void conv_h(const float* __restrict__ src, __half* __restrict__ hi,
                       int Mrows, int K, int Kpad, int ldo, int off)
{
    int idx = blockIdx.x * blockDim.x + threadIdx.x;
    if (idx >= Mrows * Kpad) return;
    int m = idx / Kpad, k = idx - m * Kpad;
    float v = (k < K) ? src[(size_t)m * K + k] : 0.f;
    hi[(size_t)m * ldo + off + k] = __float2half(v);
}

// ================= one-shot weight prep =================
#define T0 (256*352)
#define T1 (512*512)
#define T2 (256*256)
#define T3 (256*256)
#define T4 (384*256)
#define T5 (128*256)
#define T6 (512*288)
#define T7 (384+512+512+128)
#define TTOT (T0+T1+T2+T3+T4+T5+T6+T7)

__global__ void prep_all(const float* __restrict__ W1,  const float* __restrict__ Wih,
                         const float* __restrict__ Whh, const float* __restrict__ Wp1,
                         const float* __restrict__ Wp2, const float* __restrict__ Wq,
                         const float* __restrict__ Wk,  const float* __restrict__ Wg1,
                         const float* __restrict__ Wd1,
                         const float* __restrict__ bp1, const float* __restrict__ bq,
                         const float* __restrict__ bg1, const float* __restrict__ bd1,
                         const float* __restrict__ bih, const float* __restrict__ bhh,
                         const float* __restrict__ bp2,
                         __half* __restrict__ W1h,  __half* __restrict__ Brzh,
                         __half* __restrict__ Wnih, __half* __restrict__ Wnhh,
                         __half* __restrict__ Bpqh, __half* __restrict__ Wp2h,
                         __half* __restrict__ Bgdh,
                         float* __restrict__ pbpq, float* __restrict__ pbgd,
                         float* __restrict__ pbrz, float* __restrict__ pbp2p)
{
    int idx = blockIdx.x * blockDim.x + threadIdx.x;
    if (idx >= TTOT) return;
    float src;
    __half* dst;
    int off;
    if (idx < T0) {
        off = idx;
        int k = off % 352;
        src = (k < 322) ? W1[(off / 352) * 322 + k] : 0.f;
        dst = W1h;
    } else if (idx < T0 + T1) {
        off = idx - T0;
        int n = off >> 9, k = off & 511;
        src = (k < 256) ? Wih[n * 256 + k] : Whh[n * 256 + (k - 256)];
        dst = Brzh;
    } else if (idx < T0 + T1 + T2) {
        off = idx - T0 - T1;
        src = Wih[512 * 256 + off];
        dst = Wnih;
    } else if (idx < T0 + T1 + T2 + T3) {
        off = idx - T0 - T1 - T2;
        src = Whh[512 * 256 + off];
        dst = Wnhh;
    } else if (idx < T0 + T1 + T2 + T3 + T4) {
        off = idx - T0 - T1 - T2 - T3;
        int rr = off >> 8, cc = off & 255;
        if (rr < 256) src = Wp1[rr * 256 + cc];
        else if (rr < 320) src = Wq[(rr - 256) * 256 + cc];
        else src = Wk[(size_t)(rr - 320) * (HID + REL) + cc];
        dst = Bpqh;
    } else if (idx < T0 + T1 + T2 + T3 + T4 + T5) {
        off = idx - T0 - T1 - T2 - T3 - T4;
        int n = off >> 8;
        src = (n < NA) ? Wp2[n * 256 + (off & 255)] : 0.f;
        dst = Wp2h;
    } else if (idx < T0 + T1 + T2 + T3 + T4 + T5 + T6) {
        off = idx - T0 - T1 - T2 - T3 - T4 - T5;
        int rr = off / 288, cc = off % 288;
        src = (rr < 256) ? Wg1[rr * 288 + cc] : Wd1[(rr - 256) * 288 + cc];
        dst = Bgdh;
    } else {
        off = idx - (T0 + T1 + T2 + T3 + T4 + T5 + T6);
        if (off < 384) {
            pbpq[off] = (off < 256) ? bp1[off] : ((off < 320) ? bq[off - 256] : 0.f);
        } else if (off < 896) {
            int o = off - 384; pbgd[o] = (o < 256) ? bg1[o] : bd1[o - 256];
        } else if (off < 1408) {
            int o = off - 896; pbrz[o] = bih[o] + bhh[o];
        } else {
            int o = off - 1408; pbp2p[o] = (o < NA) ? bp2[o] : 0.f;
        }
        return;
    }
    dst[off] = __float2half(src);
}

// ================= GRU =================
__global__ void gru_kernel(const float* __restrict__ rz, const float* __restrict__ inn,
                           const float* __restrict__ hn, const float* __restrict__ hin,
                           float* __restrict__ hout,
                           __half* __restrict__ hh, __half* __restrict__ fh,
                           int total)
{
    int idx = blockIdx.x * blockDim.x + threadIdx.x;
    if (idx >= total) return;
    int r = idx >> 8, c = idx & 255;
    size_t rb = (size_t)r * 512;
    float rg = 1.f / (1.f + expf(-rz[rb + c]));
    float zg = 1.f / (1.f + expf(-rz[rb + 256 + c]));
    float ng = tanhf(inn[idx] + rg * hn[idx]);
    float v = (1.f - zg) * ng + zg * hin[idx];
    hout[idx] = v;
    __half h = __float2half(v);
    hh[idx] = h;
    fh[(size_t)r * 288 + c] = h;
}

// ================= logits post (padded logits, ld=128) =================
__global__ void __launch_bounds__(256)
logits_post(const float* __restrict__ logits, const float* __restrict__ Wv,
            const float* __restrict__ bv,
            float* __restrict__ out, float* __restrict__ attack,
            float* __restrict__ sender)
{
    __shared__ float Wvs[32 * 29];
    __shared__ float bvs[32];
    __shared__ float vs[8][29];
    int tid = threadIdx.x;
    for (int t = tid; t < 32 * 29; t += 256) Wvs[t] = Wv[t];
    if (tid < 32) bvs[tid] = bv[tid];
    int w = tid >> 5, l = tid & 31;
    int row = blockIdx.x * 8 + w;
    const float* lrow = logits + (size_t)row * 128;
    float al = (l < 27) ? lrow[6 + l] : -INFINITY;
    float mx = al;
#pragma unroll
    for (int o = 16; o > 0; o >>= 1) mx = fmaxf(mx, __shfl_xor_sync(0xffffffffu, mx, o));
    float e = (l < 27) ? expf(al - mx) : 0.f;
    float sum = e;
#pragma unroll
    for (int o = 16; o > 0; o >>= 1) sum += __shfl_xor_sync(0xffffffffu, sum, o);
    float inv = 1.f / sum;
    if (l < 27) vs[w][l] = e * inv;
    if (l == 27) vs[w][27] = 1.0f;
    if (l == 28) vs[w][28] = inv;
    if (l < 27) attack[(size_t)row * 27 + l] = al;
    if (l < 6)  out[(size_t)row * 33 + l] = lrow[l];
    __syncthreads();
    float s = bvs[l];
#pragma unroll
    for (int r = 0; r < 29; r++) s += vs[w][r] * Wvs[l * 29 + r];
    sender[(size_t)row * 32 + l] = s;
}

// ================= qr / qb precompute =================
__global__ void qr_kernel(const float* __restrict__ qk, const float* __restrict__ Wk,
                          const float* __restrict__ bk,
                          float* __restrict__ qr, float* __restrict__ qb, int rows)
{
    int idx = blockIdx.x * blockDim.x + threadIdx.x;
    if (idx >= rows * 4) return;
    int row = idx >> 2, h = idx & 3;
    const float* qp = qk + (size_t)row * 128 + h * 16;
    float acc[5] = {0.f, 0.f, 0.f, 0.f, 0.f};
    float accb = 0.f;
#pragma unroll
    for (int d = 0; d < 16; d++) {
        float qd = qp[d];
        const float* wrow = Wk + (size_t)(h * 16 + d) * (HID + REL) + HID;
#pragma unroll
        for (int r = 0; r < 5; r++) acc[r] += qd * wrow[r];
        accb += qd * bk[h * 16 + d];
    }
#pragma unroll
    for (int r = 0; r < 5; r++) qr[(size_t)row * 20 + h * 5 + r] = acc[r];
    qb[(size_t)row * 4 + h] = accb;
}

// ================= batched attention =================
__global__ void __launch_bounds__(256)
attn_batch(const float* __restrict__ qk, const float* __restrict__ qr,
           const float* __restrict__ qb, const float* __restrict__ rel,
           const float* __restrict__ sender,
           const float* __restrict__ nullk, const float* __restrict__ nullv,
           const float* __restrict__ ln_g, const float* __restrict__ ln_b,
           __half* __restrict__ fh)
{
    __shared__ float qk_s[27 * 128];
    __shared__ float sender_s[27 * 32];
    __shared__ float rel_s[27 * 27 * 5];
    __shared__ float qr_s[27 * 20];
    __shared__ float qb_s[27 * 4];
    __shared__ float nk_s[64];
    __shared__ float nv_s[32];
    __shared__ float sc[27 * 112];

    const int b = blockIdx.x;
    const int tid = threadIdx.x;
    const size_t rbase = (size_t)b * 27;

    for (int t = tid; t < 27 * 128; t += 256) qk_s[t] = qk[rbase * 128 + t];
    for (int t = tid; t < 27 * 32; t += 256) sender_s[t] = sender[rbase * 32 + t];
    for (int t = tid; t < 27 * 27 * 5; t += 256) rel_s[t] = rel[(size_t)b * (27 * 27 * 5) + t];
    for (int t = tid; t < 27 * 20; t += 256) qr_s[t] = qr[rbase * 20 + t];
    for (int t = tid; t < 27 * 4; t += 256) qb_s[t] = qb[rbase * 4 + t];
    if (tid < 64) nk_s[tid] = nullk[tid];
    if (tid >= 64 && tid < 96) nv_s[tid - 64] = nullv[tid - 64];
    __syncthreads();

    for (int t = tid; t < 27 * 112; t += 256) {
        int i = t / 112;
        int rem = t - i * 112;
        int j = rem >> 2, h = rem & 3;
        float s;
        if (j == 27) {
            float d = 0.f;
#pragma unroll
            for (int dd = 0; dd < 16; dd++) d += qk_s[i * 128 + h * 16 + dd] * nk_s[h * 16 + dd];
            s = 0.25f * d;
        } else if (j == i) {
            s = NEG;
        } else {
            float d = qb_s[i * 4 + h];
#pragma unroll
            for (int dd = 0; dd < 16; dd++)
                d += qk_s[i * 128 + h * 16 + dd] * qk_s[j * 128 + 64 + h * 16 + dd];
            const float* rr = &rel_s[(i * 27 + j) * 5];
#pragma unroll
            for (int r = 0; r < 5; r++) d += qr_s[i * 20 + h * 5 + r] * rr[r];
            s = 0.25f * d;
        }
        sc[t] = s;
    }
    __syncthreads();

    for (int t = tid; t < 108; t += 256) {
        int i = t >> 2, h = t & 3;
        float* scp = &sc[i * 112 + h];
        float t0 = -INFINITY, t1 = -INFINITY, t2 = -INFINITY, t3 = -INFINITY;
#pragma unroll
        for (int j = 0; j < 28; j++) {
            float v = scp[j * 4];
            if (v > t0)      { t3 = t2; t2 = t1; t1 = t0; t0 = v; }
            else if (v > t1) { t3 = t2; t2 = t1; t1 = v; }
            else if (v > t2) { t3 = t2; t2 = v; }
            else if (v > t3) { t3 = v; }
        }
        float thr = t3, mxv = t0, sum = 0.f;
        float e[28];
#pragma unroll
        for (int j = 0; j < 28; j++) {
            float v = scp[j * 4];
            float ev = (v >= thr) ? expf(v - mxv) : 0.f;
            e[j] = ev; sum += ev;
        }
        float inv = 1.f / sum;
#pragma unroll
        for (int j = 0; j < 28; j++) scp[j * 4] = e[j] * inv;
    }
    __syncthreads();

    int w = tid >> 5, l = tid & 31;
    int h = l >> 3;
    for (int i = w; i < 27; i += 8) {
        const float* scp = &sc[i * 112];
        float m = scp[108 + h] * nv_s[l];
#pragma unroll
        for (int j = 0; j < 27; j++) m += scp[j * 4 + h] * sender_s[j * 32 + l];
        float s = m, s2 = m * m;
#pragma unroll
        for (int o = 16; o > 0; o >>= 1) {
            s  += __shfl_xor_sync(0xffffffffu, s, o);
            s2 += __shfl_xor_sync(0xffffffffu, s2, o);
        }
        float mu = s * (1.f / 32.f);
        float var = s2 * (1.f / 32.f) - mu * mu;
        float nm = (m - mu) * rsqrtf(var + 1e-5f) * ln_g[l] + ln_b[l];
        fh[(rbase + i) * 288 + 256 + l] = __float2half(nm);
    }
}

// ================= final (32 rows per block) =================
__global__ void __launch_bounds__(256)
final_kernel(const float* __restrict__ gd,
             const float* __restrict__ Wg2, const float* __restrict__ bg2,
             const float* __restrict__ Wd2, const float* __restrict__ bd2,
             const float* __restrict__ attack,
             float* __restrict__ out)
{
    __shared__ float Wd2s[256 * 28];
    __shared__ float wg2s[256];
    int tid = threadIdx.x;
    for (int t = tid; t < 27 * 256; t += 256) {
        int l = t >> 8, k = t & 255;
        Wd2s[k * 28 + l] = Wd2[t];
    }
    if (tid < 256) wg2s[tid] = Wg2[tid];
    __syncthreads();

    int w = tid >> 5, l = tid & 31;
    const float bg2v = bg2[0];
    const float bd2v = (l < 27) ? bd2[l] : 0.f;
#pragma unroll
    for (int rr = 0; rr < 4; rr++) {
        int row = blockIdx.x * 32 + rr * 8 + w;
        const float* g1r = gd + (size_t)row * 512;
        const float* d1r = g1r + 256;
        float gs = 0.f;
#pragma unroll
        for (int i = 0; i < 8; i++) gs += g1r[l + i * 32] * wg2s[l + i * 32];
#pragma unroll
        for (int o = 16; o > 0; o >>= 1) gs += __shfl_xor_sync(0xffffffffu, gs, o);
        float gate = 1.f / (1.f + expf(-(gs + bg2v)));
        if (l < 27) {
            float d = bd2v;
#pragma unroll 8
            for (int k = 0; k < 256; k++) d += d1r[k] * Wd2s[k * 28 + l];
            out[(size_t)row * 33 + 6 + l] = attack[(size_t)row * 27 + l] + FUSE_SCALE * gate * d;
        }
    }
}

// ================= host launcher =================
static float* sym(const void* symbol)
{
    void* p = nullptr;
    cudaGetSymbolAddress(&p, symbol);
    return (float*)p;
}
static __half* symh(const void* symbol)
{
    void* p = nullptr;
    cudaGetSymbolAddress(&p, symbol);
    return (__half*)p;
}

extern "C" void kernel_launch(void* const* d_in, const int* in_sizes, int n_in,
                              void* d_out, int out_size)
{
    const float* inputs = (const float*)d_in[0];
    const float* hidden = (const float*)d_in[1];
    const float* rel    = (const float*)d_in[2];
    const float* W1     = (const float*)d_in[3];
    const float* b1     = (const float*)d_in[4];
    const float* Wih    = (const float*)d_in[5];
    const float* bih    = (const float*)d_in[6];
    const float* Whh    = (const float*)d_in[7];
    const float* bhh    = (const float*)d_in[8];
    const float* Wp1    = (const float*)d_in[9];
    const float* bp1    = (const float*)d_in[10];
    const float* Wp2    = (const float*)d_in[11];
    const float* bp2    = (const float*)d_in[12];
    const float* Wq     = (const float*)d_in[13];
    const float* bq     = (const float*)d_in[14];
    const float* Wk     = (const float*)d_in[15];
    const float* bk     = (const float*)d_in[16];
    const float* Wv     = (const float*)d_in[17];
    const float* bv     = (const float*)d_in[18];
    const float* ln_g   = (const float*)d_in[19];
    const float* ln_b   = (const float*)d_in[20];
    const float* Wg1    = (const float*)d_in[21];
    const float* bg1    = (const float*)d_in[22];
    const float* Wg2    = (const float*)d_in[23];
    const float* bg2    = (const float*)d_in[24];
    const float* Wd1    = (const float*)d_in[25];
    const float* bd1    = (const float*)d_in[26];
    const float* Wd2    = (const float*)d_in[27];
    const float* bd2    = (const float*)d_in[28];
    const float* nullk  = (const float*)d_in[29];
    const float* nullv  = (const float*)d_in[30];

    const int rows = in_sizes[0] / INW;    // 27648
    const int bs = rows / Nn;
    float* out = (float*)d_out;

    float* prz     = sym(g_rz);
    float* pinn    = sym(g_inn);
    float* phn     = sym(g_hn);
    float* plgp    = sym(g_lgp);
    float* pattack = sym(g_attack);
    float* psender = sym(g_sender);
    float* pqk     = sym(g_qk);
    float* pqr     = sym(g_qr);
    float* pqb     = sym(g_qb);
    float* pgd     = sym(g_gd);
    float* pbpq    = sym(g_bpq);
    float* pbgd    = sym(g_bgd);
    float* pbrz    = sym(g_brz);
    float* pbp2p   = sym(g_bp2p);

    __half *pW1h = symh(g_W1h);
    __half *pBrzh = symh(g_Brzh);
    __half *pWnih = symh(g_Wnih);
    __half *pWnhh = symh(g_Wnhh);
    __half *pBpqh = symh(g_Bpqh);
    __half *pWp2h = symh(g_Wp2h);
    __half *pBgdh = symh(g_Bgdh);
    __half *pinh = symh(g_inh);
    __half *pcath = symh(g_cath);
    __half *phh = symh(g_hh);
    __half *pph = symh(g_ph);
    __half *pfh = symh(g_fh);

    float* hout = (out_size >= rows * (NA + HID)) ? out + (size_t)rows * NA : sym(g_hfb);

    const int MB = rows / 128;   // 216

    cudaFuncSetAttribute((const void*)gemm_mma<EPI_BIAS>,        cudaFuncAttributeMaxDynamicSharedMemorySize, GSMEM);
    cudaFuncSetAttribute((const void*)gemm_mma<EPI_PLANES_RELU>, cudaFuncAttributeMaxDynamicSharedMemorySize, GSMEM);
    cudaFuncSetAttribute((const void*)gemm_mma<EPI_MIX>,         cudaFuncAttributeMaxDynamicSharedMemorySize, GSMEM);
    cudaFuncSetAttribute((const void*)gemm_mma<EPI_BIAS_RELU>,   cudaFuncAttributeMaxDynamicSharedMemorySize, GSMEM);

    // side stream + fork/join events
    static cudaStream_t s1 = nullptr;
    static cudaEvent_t e0 = nullptr, eH = nullptr, eN = nullptr, e2 = nullptr, eQ = nullptr;
    if (!s1) {
        cudaStreamCreateWithFlags(&s1, cudaStreamNonBlocking);
        cudaEventCreateWithFlags(&e0, cudaEventDisableTiming);
        cudaEventCreateWithFlags(&eH, cudaEventDisableTiming);
        cudaEventCreateWithFlags(&eN, cudaEventDisableTiming);
        cudaEventCreateWithFlags(&e2, cudaEventDisableTiming);
        cudaEventCreateWithFlags(&eQ, cudaEventDisableTiming);
    }

    // --- prep (stream 0) ---
    prep_all<<<(TTOT + 255) / 256, 256>>>(W1, Wih, Whh, Wp1, Wp2, Wq, Wk, Wg1, Wd1,
                                          bp1, bq, bg1, bd1, bih, bhh, bp2,
                                          pW1h, pBrzh, pWnih, pWnhh, pBpqh, pWp2h, pBgdh,
                                          pbpq, pbgd, pbrz, pbp2p);
    conv_h<<<(rows * 352 + 255) / 256, 256>>>(inputs, pinh, rows, 322, 352, 352, 0);

    // fork: s1 does conv(hidden) -> hn GEMM
    cudaEventRecord(e0, 0);
    cudaStreamWaitEvent(s1, e0, 0);
    conv_h<<<(rows * 256 + 255) / 256, 256, 0, s1>>>(hidden, pcath, rows, 256, 256, 512, 256);
    cudaEventRecord(eH, s1);
    gemm_mma<EPI_BIAS><<<dim3(2, MB), 256, GSMEM, s1>>>(pcath + 256, 512, pWnhh, 256,
                                                        bhh + 512, phn, nullptr, 256, 8, 0);
    cudaEventRecord(eN, s1);

    // main chain (stream 0)
    gemm_mma<EPI_PLANES_RELU><<<dim3(2, MB), 256, GSMEM>>>(pinh, 352, pW1h, 352, b1,
                                                           nullptr, pcath, 512, 11, 0);
    cudaStreamWaitEvent(0, eH, 0);
    gemm_mma<EPI_BIAS><<<dim3(4, MB), 256, GSMEM>>>(pcath, 512, pBrzh, 512, pbrz,
                                                    prz, nullptr, 512, 16, 0);
    gemm_mma<EPI_BIAS><<<dim3(2, MB), 256, GSMEM>>>(pcath, 512, pWnih, 256, bih + 512,
                                                    pinn, nullptr, 256, 8, 0);
    cudaStreamWaitEvent(0, eN, 0);
    gru_kernel<<<(rows * 256 + 255) / 256, 256>>>(prz, pinn, phn, hidden, hout, phh, pfh, rows * 256);
    // merged [p-planes | qk]
    gemm_mma<EPI_MIX><<<dim3(3, MB), 256, GSMEM>>>(phh, 256, pBpqh, 256, pbpq,
                                                   pqk, pph, 256, 8, 128);
    cudaEventRecord(e2, 0);
    cudaStreamWaitEvent(s1, e2, 0);
    qr_kernel<<<(rows * 4 + 127) / 128, 128, 0, s1>>>(pqk, Wk, bk, pqr, pqb, rows);
    cudaEventRecord(eQ, s1);
    gemm_mma<EPI_BIAS><<<dim3(1, MB), 256, GSMEM>>>(pph, 256, pWp2h, 256, pbp2p,
                                                    plgp, nullptr, 128, 8, 0);
    logits_post<<<rows / 8, 256>>>(plgp, Wv, bv, out, pattack, psender);
    cudaStreamWaitEvent(0, eQ, 0);
    attn_batch<<<bs, 256>>>(pqk, pqr, pqb, rel, psender, nullk, nullv, ln_g, ln_b, pfh);
    gemm_mma<EPI_BIAS_RELU><<<dim3(4, MB), 256, GSMEM>>>(pfh, 288, pBgdh, 288, pbgd,
                                                         pgd, nullptr, 512, 9, 0);
    final_kernel<<<rows / 32, 256>>>(pgd, Wg2, bg2, Wd2, bd2, pattack, out);
}